// round 17
// baseline (speedup 1.0000x reference)
#include <cuda_runtime.h>
#include <cuda_bf16.h>
#include <cuda_fp16.h>
#include <math.h>
#include <stdint.h>

// Problem constants
constexpr int SEQ   = 1024;
constexpr int DM    = 1024;
constexpr int NHEAD = 16;
constexpr int HDIM  = 64;
constexpr int NB    = 4;
constexpr int MR    = NB * SEQ;

constexpr size_t ACT = (size_t)MR * DM;   // one activation slice
constexpr size_t WSZ = (size_t)DM * DM;   // one weight slice

// ---------------- scratch (device globals; no allocation allowed) ----------
__device__ __half g_s [(size_t)NB * NHEAD * SEQ * SEQ];   // fp16 scores (b,h,q,j)
__device__ float g_bqkv[3 * DM];                          // bq|bk|bv

__device__ __nv_bfloat16 g_acth[3 * ACT];   // y | x | x  (hi)
__device__ __nv_bfloat16 g_actl[3 * ACT];
__device__ __nv_bfloat16 g_wh3[3 * WSZ];    // wq | wk | wv (hi)
__device__ __nv_bfloat16 g_wl3[3 * WSZ];
__device__ __nv_bfloat16 g_qkvh[3 * ACT];   // q | k | v (hi)
__device__ __nv_bfloat16 g_qkvl[3 * ACT];
__device__ __nv_bfloat16 g_vth[(size_t)MR * DM];   // v^T per (b,h): [b][h][d][j]
__device__ __nv_bfloat16 g_vtl[(size_t)MR * DM];
__device__ __nv_bfloat16 g_avh[(size_t)MR * DM];
__device__ __nv_bfloat16 g_avl[(size_t)MR * DM];
__device__ __nv_bfloat16 g_atth[(size_t)NHEAD * SEQ * SEQ];
__device__ __nv_bfloat16 g_attl[(size_t)NHEAD * SEQ * SEQ];
__device__ __nv_bfloat16 g_woh[WSZ];
__device__ __nv_bfloat16 g_wol[WSZ];

// ===========================================================================
// helpers
// ===========================================================================
__device__ __forceinline__ uint32_t smem_u32(const void* p) {
    uint32_t r;
    asm("{ .reg .u64 t; cvta.to.shared.u64 t, %1; cvt.u32.u64 %0, t; }"
        : "=r"(r) : "l"(p));
    return r;
}
__device__ __forceinline__ void cp16(uint32_t dst, const void* src) {
    asm volatile("cp.async.cg.shared.global [%0], [%1], 16;" :: "r"(dst), "l"(src));
}
__device__ __forceinline__ void cp_commit() {
    asm volatile("cp.async.commit_group;" ::: "memory");
}
template <int N>
__device__ __forceinline__ void cp_wait() {
    asm volatile("cp.async.wait_group %0;" :: "n"(N) : "memory");
}
__device__ __forceinline__ void ldsm_x4(uint32_t* r, uint32_t addr) {
    asm volatile("ldmatrix.sync.aligned.m8n8.x4.shared.b16 {%0,%1,%2,%3}, [%4];"
        : "=r"(r[0]), "=r"(r[1]), "=r"(r[2]), "=r"(r[3]) : "r"(addr));
}
__device__ __forceinline__ void mma16816(
    float* d, const uint32_t* a, const uint32_t* b)
{
    asm volatile(
        "mma.sync.aligned.m16n8k16.row.col.f32.bf16.bf16.f32 "
        "{%0,%1,%2,%3}, {%4,%5,%6,%7}, {%8,%9}, {%0,%1,%2,%3};"
        : "+f"(d[0]), "+f"(d[1]), "+f"(d[2]), "+f"(d[3])
        : "r"(a[0]), "r"(a[1]), "r"(a[2]), "r"(a[3]), "r"(b[0]), "r"(b[1]));
}

// ===========================================================================
// input splits into sliced buffers (1 launch, grid.y = 8 segments)
// ===========================================================================
__global__ __launch_bounds__(256) void split8_kernel(
    const float* __restrict__ y,  const float* __restrict__ x,
    const float* __restrict__ wq, const float* __restrict__ wk,
    const float* __restrict__ wv, const float* __restrict__ wo,
    const float* __restrict__ bq, const float* __restrict__ bk,
    const float* __restrict__ bv,
    __nv_bfloat16* acth, __nv_bfloat16* actl,
    __nv_bfloat16* wh3,  __nv_bfloat16* wl3,
    __nv_bfloat16* woh,  __nv_bfloat16* wol,
    float* bqkv)
{
    const int seg = blockIdx.y;
    const int tid = threadIdx.x;

    if (seg == 7) {
        if (blockIdx.x == 0 && tid < 256) {
            ((float4*)bqkv)[tid]       = ((const float4*)bq)[tid];
            ((float4*)bqkv)[tid + 256] = ((const float4*)bk)[tid];
            ((float4*)bqkv)[tid + 512] = ((const float4*)bv)[tid];
        }
        return;
    }

    const float* in; __nv_bfloat16 *hi, *lo; int n4;
    if (seg < 3) {
        in = (seg == 0) ? y : x;
        hi = acth + (size_t)seg * ACT;
        lo = actl + (size_t)seg * ACT;
        n4 = (int)(ACT / 4);
    } else if (seg < 6) {
        in = (seg == 3) ? wq : (seg == 4) ? wk : wv;
        hi = wh3 + (size_t)(seg - 3) * WSZ;
        lo = wl3 + (size_t)(seg - 3) * WSZ;
        n4 = (int)(WSZ / 4);
    } else {
        in = wo; hi = woh; lo = wol; n4 = (int)(WSZ / 4);
    }

    int i = blockIdx.x * blockDim.x + tid;
    if (i >= n4) return;
    float4 v = ((const float4*)in)[i];
    __nv_bfloat16 h0 = __float2bfloat16(v.x);
    __nv_bfloat16 h1 = __float2bfloat16(v.y);
    __nv_bfloat16 h2 = __float2bfloat16(v.z);
    __nv_bfloat16 h3 = __float2bfloat16(v.w);
    ushort4 H, L;
    H.x = __bfloat16_as_ushort(h0); H.y = __bfloat16_as_ushort(h1);
    H.z = __bfloat16_as_ushort(h2); H.w = __bfloat16_as_ushort(h3);
    L.x = __bfloat16_as_ushort(__float2bfloat16(v.x - __bfloat162float(h0)));
    L.y = __bfloat16_as_ushort(__float2bfloat16(v.y - __bfloat162float(h1)));
    L.z = __bfloat16_as_ushort(__float2bfloat16(v.z - __bfloat162float(h2)));
    L.w = __bfloat16_as_ushort(__float2bfloat16(v.w - __bfloat162float(h3)));
    ((ushort4*)hi)[i] = H;
    ((ushort4*)lo)[i] = L;
}

// ===========================================================================
// bf16 transpose of v hi/lo:  vt[b][h][d][j] = v[b*S+j][h*64+d]
// ===========================================================================
__global__ __launch_bounds__(256) void transpose_v_kernel(
    const __nv_bfloat16* __restrict__ vh, const __nv_bfloat16* __restrict__ vl,
    __nv_bfloat16* __restrict__ vth, __nv_bfloat16* __restrict__ vtl)
{
    __shared__ uint16_t th[64][72];
    __shared__ uint16_t tl[64][72];
    const int bh = blockIdx.y;
    const int b  = bh >> 4;
    const int h  = bh & 15;
    const int j0 = blockIdx.x * 64;
    const int tid = threadIdx.x;

#pragma unroll
    for (int i = 0; i < 4; i++) {
        int idx = tid + i * 256;
        int j   = idx >> 4;
        int dq  = (idx & 15) * 4;
        size_t off = (size_t)(b * SEQ + j0 + j) * DM + h * HDIM + dq;
        ushort4 a = *(const ushort4*)((const uint16_t*)vh + off);
        ushort4 c = *(const ushort4*)((const uint16_t*)vl + off);
        th[dq + 0][j] = a.x; th[dq + 1][j] = a.y; th[dq + 2][j] = a.z; th[dq + 3][j] = a.w;
        tl[dq + 0][j] = c.x; tl[dq + 1][j] = c.y; tl[dq + 2][j] = c.z; tl[dq + 3][j] = c.w;
    }
    __syncthreads();

    const int d  = tid >> 2;
    const int jq = (tid & 3) * 16;
    uint16_t* oh = (uint16_t*)vth + ((size_t)bh * HDIM + d) * SEQ + j0 + jq;
    uint16_t* ol = (uint16_t*)vtl + ((size_t)bh * HDIM + d) * SEQ + j0 + jq;
#pragma unroll
    for (int c = 0; c < 4; c++) {
        ushort4 A, B;
        A.x = th[d][jq + c * 4 + 0]; A.y = th[d][jq + c * 4 + 1];
        A.z = th[d][jq + c * 4 + 2]; A.w = th[d][jq + c * 4 + 3];
        B.x = tl[d][jq + c * 4 + 0]; B.y = tl[d][jq + c * 4 + 1];
        B.z = tl[d][jq + c * 4 + 2]; B.w = tl[d][jq + c * 4 + 3];
        *(ushort4*)(oh + c * 4) = A;
        *(ushort4*)(ol + c * 4) = B;
    }
}

// ===========================================================================
// Generic bf16x3 compensated GEMM, ldmatrix fragments, cp.async 2-stage,
// single-sync mainloop. Output modes: 0 = fp32, 1 = bf16 hi/lo, 2 = fp16.
// ===========================================================================
#define SMM_STRIDE 40   // 32 k elems + 8 pad (bf16)

template <int NT, int OMODE>
__global__ __launch_bounds__(256, 2) void mm3_kernel(
    const __nv_bfloat16* __restrict__ Ah, const __nv_bfloat16* __restrict__ Al,
    size_t asb, size_t ash, int lda,
    const __nv_bfloat16* __restrict__ Wh, const __nv_bfloat16* __restrict__ Wl,
    size_t wsb, size_t wsh, int ldw,
    const float* __restrict__ bias, int bsh,
    float* __restrict__ C, __nv_bfloat16* __restrict__ Ch, __nv_bfloat16* __restrict__ Cl,
    __half* __restrict__ Chalf,
    size_t csb, size_t csh, int ldc,
    int K, float scale)
{
    constexpr int NATOMS  = NT / 16;
    constexpr int A_BYTES = 128 * SMM_STRIDE * 2;
    constexpr int W_BYTES = NT * SMM_STRIDE * 2;
    constexpr int STAGE   = 2 * A_BYTES + 2 * W_BYTES;

    extern __shared__ char smem[];
    const uint32_t sbase = smem_u32(smem);

    const int tid  = threadIdx.x;
    const int wid  = tid >> 5;
    const int lane = tid & 31;
    const int gid  = lane >> 2;
    const int tig  = lane & 3;
    const int wm   = wid & 3;
    const int wn   = wid >> 2;
    const int m0   = blockIdx.y * 128;
    const int n0   = blockIdx.x * NT;
    const int z    = blockIdx.z;
    const int zb   = z >> 4;
    const int zh   = z & 15;

    const __nv_bfloat16* pAh = Ah + (size_t)zb * asb + (size_t)zh * ash;
    const __nv_bfloat16* pAl = Al + (size_t)zb * asb + (size_t)zh * ash;
    const __nv_bfloat16* pWh = Wh + (size_t)zb * wsb + (size_t)zh * wsh;
    const __nv_bfloat16* pWl = Wl + (size_t)zb * wsb + (size_t)zh * wsh;

    const int a_r = lane & 15;
    const int a_c = (lane >> 4) << 3;
    const int w_r = (lane & 7) + ((lane & 16) >> 1);
    const int w_c = ((lane >> 3) & 1) << 3;

    float acc[2][NATOMS][4];
#pragma unroll
    for (int i = 0; i < 2; i++)
#pragma unroll
        for (int j = 0; j < NATOMS; j++)
#pragma unroll
            for (int c = 0; c < 4; c++) acc[i][j][c] = 0.f;

    const int nk = K >> 5;

    auto load_stage = [&](int s, int k0) {
        uint32_t st = sbase + s * STAGE;
#pragma unroll
        for (int i = 0; i < 2; i++) {
            int idx = tid + i * 256;
            int row = idx >> 2;
            int kq  = idx & 3;
            uint32_t doff = (row * SMM_STRIDE + kq * 8) * 2;
            cp16(st + doff,           pAh + (size_t)(m0 + row) * lda + k0 + kq * 8);
            cp16(st + A_BYTES + doff, pAl + (size_t)(m0 + row) * lda + k0 + kq * 8);
        }
#pragma unroll
        for (int i = 0; i < (NT == 128 ? 2 : 1); i++) {
            int idx = tid + i * 256;
            int row = idx >> 2;
            int kq  = idx & 3;
            uint32_t doff = (row * SMM_STRIDE + kq * 8) * 2;
            cp16(st + 2 * A_BYTES + doff,           pWh + (size_t)(n0 + row) * ldw + k0 + kq * 8);
            cp16(st + 2 * A_BYTES + W_BYTES + doff, pWl + (size_t)(n0 + row) * ldw + k0 + kq * 8);
        }
    };

    load_stage(0, 0);
    cp_commit();

    for (int c0 = 0; c0 < nk; c0++) {
        cp_wait<0>();
        __syncthreads();
        if (c0 + 1 < nk) { load_stage((c0 + 1) & 1, (c0 + 1) * 32); cp_commit(); }

        uint32_t st  = sbase + (c0 & 1) * STAGE;
        uint32_t sAh = st;
        uint32_t sAl = st + A_BYTES;
        uint32_t sWh = st + 2 * A_BYTES;
        uint32_t sWl = st + 2 * A_BYTES + W_BYTES;

#pragma unroll
        for (int ks = 0; ks < 2; ks++) {
            const int cb = ks * 16;
            uint32_t afh[2][4], afl[2][4], wf[NATOMS][2];

#pragma unroll
            for (int i = 0; i < 2; i++) {
                int r = wm * 32 + i * 16 + a_r;
                ldsm_x4(afh[i], sAh + (r * SMM_STRIDE + cb + a_c) * 2);
            }
#pragma unroll
            for (int jp = 0; jp < NATOMS / 2; jp++) {
                int n = wn * (NT / 2) + jp * 16 + w_r;
                ldsm_x4(&wf[2 * jp][0], sWh + (n * SMM_STRIDE + cb + w_c) * 2);
            }
#pragma unroll
            for (int i = 0; i < 2; i++)
#pragma unroll
                for (int j = 0; j < NATOMS; j++) mma16816(acc[i][j], afh[i], wf[j]);

#pragma unroll
            for (int i = 0; i < 2; i++) {
                int r = wm * 32 + i * 16 + a_r;
                ldsm_x4(afl[i], sAl + (r * SMM_STRIDE + cb + a_c) * 2);
            }
#pragma unroll
            for (int i = 0; i < 2; i++)
#pragma unroll
                for (int j = 0; j < NATOMS; j++) mma16816(acc[i][j], afl[i], wf[j]);

#pragma unroll
            for (int jp = 0; jp < NATOMS / 2; jp++) {
                int n = wn * (NT / 2) + jp * 16 + w_r;
                ldsm_x4(&wf[2 * jp][0], sWl + (n * SMM_STRIDE + cb + w_c) * 2);
            }
#pragma unroll
            for (int i = 0; i < 2; i++)
#pragma unroll
                for (int j = 0; j < NATOMS; j++) mma16816(acc[i][j], afh[i], wf[j]);
        }
    }

    // ---- epilogue (register-private; no barrier needed) ----
#pragma unroll
    for (int i = 0; i < 2; i++) {
        int row = m0 + wm * 32 + i * 16 + gid;
#pragma unroll
        for (int j = 0; j < NATOMS; j++) {
            int col = n0 + wn * (NT / 2) + j * 8 + tig * 2;
            float b0 = bias ? bias[zh * bsh + col] : 0.f;
            float b1 = bias ? bias[zh * bsh + col + 1] : 0.f;
            float f0 = acc[i][j][0] * scale + b0;
            float f1 = acc[i][j][1] * scale + b1;
            float f2 = acc[i][j][2] * scale + b0;
            float f3 = acc[i][j][3] * scale + b1;
            if (OMODE == 1) {
                uint16_t* pH = (uint16_t*)Ch + (size_t)zb * csb + (size_t)zh * csh;
                uint16_t* pL = (uint16_t*)Cl + (size_t)zb * csb + (size_t)zh * csh;
                __nv_bfloat16 h0 = __float2bfloat16(f0), h1 = __float2bfloat16(f1);
                __nv_bfloat16 h2 = __float2bfloat16(f2), h3 = __float2bfloat16(f3);
                ushort2 H0 = {__bfloat16_as_ushort(h0), __bfloat16_as_ushort(h1)};
                ushort2 H1 = {__bfloat16_as_ushort(h2), __bfloat16_as_ushort(h3)};
                ushort2 L0 = {__bfloat16_as_ushort(__float2bfloat16(f0 - __bfloat162float(h0))),
                              __bfloat16_as_ushort(__float2bfloat16(f1 - __bfloat162float(h1)))};
                ushort2 L1 = {__bfloat16_as_ushort(__float2bfloat16(f2 - __bfloat162float(h2))),
                              __bfloat16_as_ushort(__float2bfloat16(f3 - __bfloat162float(h3)))};
                *(ushort2*)(pH + (size_t)row * ldc + col) = H0;
                *(ushort2*)(pH + (size_t)(row + 8) * ldc + col) = H1;
                *(ushort2*)(pL + (size_t)row * ldc + col) = L0;
                *(ushort2*)(pL + (size_t)(row + 8) * ldc + col) = L1;
            } else if (OMODE == 2) {
                __half* pC = Chalf + (size_t)zb * csb + (size_t)zh * csh;
                __half2 v0 = __floats2half2_rn(f0, f1);
                __half2 v1 = __floats2half2_rn(f2, f3);
                *(__half2*)(pC + (size_t)row * ldc + col) = v0;
                *(__half2*)(pC + (size_t)(row + 8) * ldc + col) = v1;
            } else {
                float* pC = C + (size_t)zb * csb + (size_t)zh * csh;
                *(float2*)(pC + (size_t)row * ldc + col) = make_float2(f0, f1);
                *(float2*)(pC + (size_t)(row + 8) * ldc + col) = make_float2(f2, f3);
            }
        }
    }
}

// ===========================================================================
// Dedicated scores kernel: CTA = (128 q rows, one bh), full 128x1024 row
// block. q tile smem-resident (loaded once); k tiles double-buffered through
// 8 pipelined iterations. bf16x3 mma; fp16 output scaled by 0.125.
// smem: q hi/lo 2x18432 + 2 stages x (k hi/lo 2x18432) = 110592 B
// ===========================================================================
constexpr int SC_TILE  = 18432;           // 128 rows x 72 hw x 2B
constexpr int SC_QH    = 0;
constexpr int SC_QL    = SC_TILE;
constexpr int SC_K0    = 2 * SC_TILE;     // stage s at SC_K0 + s*2*SC_TILE
constexpr int SC_TOTAL = SC_K0 + 2 * 2 * SC_TILE;   // 110592

__global__ __launch_bounds__(256, 2) void scores_kernel(
    const __nv_bfloat16* __restrict__ qh, const __nv_bfloat16* __restrict__ ql,
    const __nv_bfloat16* __restrict__ kh, const __nv_bfloat16* __restrict__ kl,
    __half* __restrict__ sc)
{
    extern __shared__ char smem[];
    const uint32_t sbase = smem_u32(smem);

    const int tid  = threadIdx.x;
    const int wid  = tid >> 5;
    const int lane = tid & 31;
    const int gid  = lane >> 2;
    const int tig  = lane & 3;
    const int wm   = wid & 3;
    const int wn   = wid >> 2;
    const int q0   = blockIdx.x * 128;
    const int bh   = blockIdx.y;
    const int b    = bh >> 4;
    const int h    = bh & 15;

    const uint16_t* pqh = (const uint16_t*)qh + ((size_t)(b * SEQ + q0)) * DM + h * HDIM;
    const uint16_t* pql = (const uint16_t*)ql + ((size_t)(b * SEQ + q0)) * DM + h * HDIM;
    const uint16_t* pkh = (const uint16_t*)kh + ((size_t)(b * SEQ)) * DM + h * HDIM;
    const uint16_t* pkl = (const uint16_t*)kl + ((size_t)(b * SEQ)) * DM + h * HDIM;

    const int a_r = lane & 15;
    const int a_c = (lane >> 4) << 3;
    const int w_r = (lane & 7) + ((lane & 16) >> 1);
    const int w_c = ((lane >> 3) & 1) << 3;

    // ---- load q tile (hi+lo), 128 rows x 64 hw, stride 72 ----
#pragma unroll
    for (int i = 0; i < 4; i++) {
        int idx = tid + i * 256;          // 0..1023
        int row = idx >> 3;
        int kq  = idx & 7;
        uint32_t doff = (row * 72 + kq * 8) * 2;
        cp16(sbase + SC_QH + doff, pqh + (size_t)row * DM + kq * 8);
        cp16(sbase + SC_QL + doff, pql + (size_t)row * DM + kq * 8);
    }

    auto load_k = [&](int s, int jt) {
        uint32_t st = sbase + SC_K0 + s * 2 * SC_TILE;
        const uint16_t* ph = pkh + (size_t)jt * 128 * DM;
        const uint16_t* pl = pkl + (size_t)jt * 128 * DM;
#pragma unroll
        for (int i = 0; i < 4; i++) {
            int idx = tid + i * 256;
            int row = idx >> 3;
            int kq  = idx & 7;
            uint32_t doff = (row * 72 + kq * 8) * 2;
            cp16(st + doff,           ph + (size_t)row * DM + kq * 8);
            cp16(st + SC_TILE + doff, pl + (size_t)row * DM + kq * 8);
        }
    };

    load_k(0, 0);
    cp_commit();

    __half* out = sc + (size_t)bh * SEQ * SEQ;

    for (int jt = 0; jt < 8; jt++) {
        cp_wait<0>();
        __syncthreads();
        if (jt + 1 < 8) { load_k((jt + 1) & 1, jt + 1); cp_commit(); }

        uint32_t sKh = sbase + SC_K0 + (jt & 1) * 2 * SC_TILE;
        uint32_t sKl = sKh + SC_TILE;

        float acc[2][8][4];
#pragma unroll
        for (int i = 0; i < 2; i++)
#pragma unroll
            for (int j = 0; j < 8; j++)
#pragma unroll
                for (int c = 0; c < 4; c++) acc[i][j][c] = 0.f;

#pragma unroll
        for (int ks = 0; ks < 4; ks++) {
            const int cb = ks * 16;
            uint32_t afh[2][4], afl[2][4], wf[8][2];

#pragma unroll
            for (int i = 0; i < 2; i++) {
                int r = wm * 32 + i * 16 + a_r;
                ldsm_x4(afh[i], sbase + SC_QH + (r * 72 + cb + a_c) * 2);
            }
#pragma unroll
            for (int jp = 0; jp < 4; jp++) {
                int n = wn * 64 + jp * 16 + w_r;
                ldsm_x4(&wf[2 * jp][0], sKh + (n * 72 + cb + w_c) * 2);
            }
#pragma unroll
            for (int i = 0; i < 2; i++)
#pragma unroll
                for (int j = 0; j < 8; j++) mma16816(acc[i][j], afh[i], wf[j]);

#pragma unroll
            for (int i = 0; i < 2; i++) {
                int r = wm * 32 + i * 16 + a_r;
                ldsm_x4(afl[i], sbase + SC_QL + (r * 72 + cb + a_c) * 2);
            }
#pragma unroll
            for (int i = 0; i < 2; i++)
#pragma unroll
                for (int j = 0; j < 8; j++) mma16816(acc[i][j], afl[i], wf[j]);

#pragma unroll
            for (int jp = 0; jp < 4; jp++) {
                int n = wn * 64 + jp * 16 + w_r;
                ldsm_x4(&wf[2 * jp][0], sKl + (n * 72 + cb + w_c) * 2);
            }
#pragma unroll
            for (int i = 0; i < 2; i++)
#pragma unroll
                for (int j = 0; j < 8; j++) mma16816(acc[i][j], afh[i], wf[j]);
        }

        // ---- fp16 epilogue for this 128x128 tile ----
#pragma unroll
        for (int i = 0; i < 2; i++) {
            int row = q0 + wm * 32 + i * 16 + gid;
#pragma unroll
            for (int j = 0; j < 8; j++) {
                int col = jt * 128 + wn * 64 + j * 8 + tig * 2;
                __half2 v0 = __floats2half2_rn(acc[i][j][0] * 0.125f, acc[i][j][1] * 0.125f);
                __half2 v1 = __floats2half2_rn(acc[i][j][2] * 0.125f, acc[i][j][3] * 0.125f);
                *(__half2*)(out + (size_t)row * SEQ + col) = v0;
                *(__half2*)(out + (size_t)(row + 8) * SEQ + col) = v1;
            }
        }
    }
}

// ===========================================================================
// Softmax over j (+mask), NaN->0, sum over batch; reads fp16 scores,
// emits bf16 hi/lo att.
// ===========================================================================
__global__ __launch_bounds__(256) void softmax_sum_kernel(
    const __half* __restrict__ s, const float* __restrict__ mask,
    __nv_bfloat16* __restrict__ atth, __nv_bfloat16* __restrict__ attl)
{
    __shared__ float red[8];

    const int h   = blockIdx.x >> 10;
    const int qi  = blockIdx.x & 1023;
    const int tid = threadIdx.x;
    const int lane = tid & 31;
    const int warp = tid >> 5;

    float mv[4];
#pragma unroll
    for (int u = 0; u < 4; u++) mv[u] = mask[(size_t)qi * SEQ + tid + u * 256];

    float facc[4] = {0.f, 0.f, 0.f, 0.f};

    for (int b = 0; b < NB; b++) {
        const __half* srow = s + (((size_t)(b * NHEAD + h)) * SEQ + qi) * SEQ;
        float rv[4];
        float m = -INFINITY;
#pragma unroll
        for (int u = 0; u < 4; u++) {
            rv[u] = __half2float(srow[tid + u * 256]) + mv[u];
            m = fmaxf(m, rv[u]);
        }
#pragma unroll
        for (int o = 16; o > 0; o >>= 1) m = fmaxf(m, __shfl_xor_sync(0xffffffffu, m, o));
        __syncthreads();
        if (lane == 0) red[warp] = m;
        __syncthreads();
        m = red[0];
#pragma unroll
        for (int w = 1; w < 8; w++) m = fmaxf(m, red[w]);

        float ssum = 0.f;
#pragma unroll
        for (int u = 0; u < 4; u++) {
            rv[u] = __expf(rv[u] - m);
            ssum += rv[u];
        }
#pragma unroll
        for (int o = 16; o > 0; o >>= 1) ssum += __shfl_xor_sync(0xffffffffu, ssum, o);
        __syncthreads();
        if (lane == 0) red[warp] = ssum;
        __syncthreads();
        ssum = 0.f;
#pragma unroll
        for (int w = 0; w < 8; w++) ssum += red[w];

        if (ssum > 0.f && isfinite(ssum)) {
            float inv = 1.f / ssum;
#pragma unroll
            for (int u = 0; u < 4; u++) facc[u] += rv[u] * inv;
        }
    }

    size_t rowoff = ((size_t)h * SEQ + qi) * SEQ;
#pragma unroll
    for (int u = 0; u < 4; u++) {
        float f = facc[u];
        __nv_bfloat16 hi = __float2bfloat16(f);
        atth[rowoff + tid + u * 256] = hi;
        attl[rowoff + tid + u * 256] = __float2bfloat16(f - __bfloat162float(hi));
    }
}

// ===========================================================================
extern "C" void kernel_launch(void* const* d_in, const int* in_sizes, int n_in,
                              void* d_out, int out_size)
{
    const float* x    = (const float*)d_in[0];
    const float* y    = (const float*)d_in[1];
    const float* mask = (const float*)d_in[2];
    const float* Wq   = (const float*)d_in[3];
    const float* bq   = (const float*)d_in[4];
    const float* Wk   = (const float*)d_in[5];
    const float* bk   = (const float*)d_in[6];
    const float* Wv   = (const float*)d_in[7];
    const float* bv   = (const float*)d_in[8];
    const float* Wo   = (const float*)d_in[9];
    const float* bo   = (const float*)d_in[10];
    float* out = (float*)d_out;

    __half* sc;
    float* bqkv;
    cudaGetSymbolAddress((void**)&sc,   g_s);
    cudaGetSymbolAddress((void**)&bqkv, g_bqkv);

    __nv_bfloat16 *acth, *actl, *wh3, *wl3, *qkvh, *qkvl;
    __nv_bfloat16 *vth, *vtl, *avh, *avl, *atth, *attl, *woh, *wol;
    cudaGetSymbolAddress((void**)&acth, g_acth); cudaGetSymbolAddress((void**)&actl, g_actl);
    cudaGetSymbolAddress((void**)&wh3, g_wh3);   cudaGetSymbolAddress((void**)&wl3, g_wl3);
    cudaGetSymbolAddress((void**)&qkvh, g_qkvh); cudaGetSymbolAddress((void**)&qkvl, g_qkvl);
    cudaGetSymbolAddress((void**)&vth, g_vth);   cudaGetSymbolAddress((void**)&vtl, g_vtl);
    cudaGetSymbolAddress((void**)&avh, g_avh);   cudaGetSymbolAddress((void**)&avl, g_avl);
    cudaGetSymbolAddress((void**)&atth, g_atth); cudaGetSymbolAddress((void**)&attl, g_attl);
    cudaGetSymbolAddress((void**)&woh, g_woh);   cudaGetSymbolAddress((void**)&wol, g_wol);

    constexpr int SMEM128 = 2 * (2 * 128 * SMM_STRIDE * 2 + 2 * 128 * SMM_STRIDE * 2); // 81920
    constexpr int SMEM64  = 2 * (2 * 128 * SMM_STRIDE * 2 + 2 * 64 * SMM_STRIDE * 2);  // 61440
    cudaFuncSetAttribute(mm3_kernel<128, 1>, cudaFuncAttributeMaxDynamicSharedMemorySize, SMEM128);
    cudaFuncSetAttribute(mm3_kernel<128, 0>, cudaFuncAttributeMaxDynamicSharedMemorySize, SMEM128);
    cudaFuncSetAttribute(mm3_kernel<64, 1>,  cudaFuncAttributeMaxDynamicSharedMemorySize, SMEM64);
    cudaFuncSetAttribute(scores_kernel,      cudaFuncAttributeMaxDynamicSharedMemorySize, SC_TOTAL);

    const size_t SDM = (size_t)SEQ * DM;
    const size_t SS  = (size_t)SEQ * SEQ;

    // ---- input splits (1 launch, 8 segments) ----
    split8_kernel<<<dim3((int)(ACT / 4 / 256), 8), 256>>>(
        y, x, Wq, Wk, Wv, Wo, bq, bk, bv,
        acth, actl, wh3, wl3, woh, wol, bqkv);

    // ---- fused QKV projections: one launch, grid.z = 3 ----
    mm3_kernel<128, 1><<<dim3(DM / 128, MR / 128, 3), 256, SMEM128>>>(
        acth, actl, 0, ACT, DM,
        wh3, wl3, 0, WSZ, DM,
        bqkv, DM,
        nullptr, qkvh, qkvl, nullptr, 0, ACT, DM, DM, 1.f);

    // ---- v transpose (bf16); v = slice 2 of qkv ----
    transpose_v_kernel<<<dim3(SEQ / 64, NB * NHEAD), 256>>>(
        qkvh + 2 * ACT, qkvl + 2 * ACT, vth, vtl);

    // ---- scores: dedicated kernel, q-tile resident, fp16 out ----
    scores_kernel<<<dim3(SEQ / 128, NB * NHEAD), 256, SC_TOTAL>>>(
        qkvh, qkvl, qkvh + ACT, qkvl + ACT, sc);

    // ---- softmax + batch-sum -> bf16 hi/lo att ----
    softmax_sum_kernel<<<NHEAD * SEQ, 256>>>(sc, mask, atth, attl);

    // ---- AV: av[b,:,h*64+d] = att_h @ vt_bh^T  (N=64, K=1024), split out ----
    mm3_kernel<64, 1><<<dim3(1, SEQ / 128, NB * NHEAD), 256, SMEM64>>>(
        atth, attl, 0, SS, SEQ,
        vth, vtl, (size_t)NHEAD * HDIM * SEQ, (size_t)HDIM * SEQ, SEQ,
        nullptr, 0,
        nullptr, avh, avl, nullptr, SDM, (size_t)HDIM, DM, SEQ, 1.f);

    // ---- output projection (fp32 out + bias) ----
    mm3_kernel<128, 0><<<dim3(DM / 128, MR / 128, 1), 256, SMEM128>>>(
        avh, avl, 0, 0, DM, woh, wol, 0, 0, DM,
        bo, 0,
        out, nullptr, nullptr, nullptr, 0, 0, DM, DM, 1.f);
}